// round 7
// baseline (speedup 1.0000x reference)
#include <cuda_runtime.h>
#include <cuda_bf16.h>
#include <cstdint>

#define L_LAYERS 20
#define ACT_LD   144       // weight plane row stride (64*2B + 16 pad)
#define WC_LD    176       // causal plane row stride (80*2B + 16 pad)
#define NTH      384       // 8 compute warps + 4 producer warps

// ---- smem layout (bytes) ----
#define WBUF0    0
#define WBUF1    55296
#define SCRATCH  110592
#define WCA_HI   110592
#define WCA_LO   121856
#define OFF_BDR  133120    // [2 buf][bd 64 | br 64] f32
#define OFF_BC   134144
#define OFF_BTOT 134400
#define OFF_BP1  134656
#define OFF_WP2  134912
#define OFF_B2   135168
#define OFF_MB   135200    // 4 mbarriers: full0, empty0, full1, empty1
#define SMEM_BYTES 135296
// causal x planes alias WBUF1
#define X_HI     55296
#define X_LO     77824

__device__ __forceinline__ uint32_t smem_u32(const void* p) {
    uint32_t a;
    asm("{ .reg .u64 t; cvta.to.shared.u64 t, %1; cvt.u32.u64 %0, t; }" : "=r"(a) : "l"(p));
    return a;
}
__device__ __forceinline__ void ldsm4(uint32_t addr, uint32_t r[4]) {
    asm volatile("ldmatrix.sync.aligned.m8n8.x4.shared.b16 {%0,%1,%2,%3}, [%4];"
                 : "=r"(r[0]), "=r"(r[1]), "=r"(r[2]), "=r"(r[3]) : "r"(addr));
}
__device__ __forceinline__ void mma16816(float d[4], const uint32_t a[4],
                                         uint32_t b0, uint32_t b1) {
    asm volatile("mma.sync.aligned.m16n8k16.row.col.f32.bf16.bf16.f32 "
                 "{%0,%1,%2,%3},{%4,%5,%6,%7},{%8,%9},{%0,%1,%2,%3};"
                 : "+f"(d[0]), "+f"(d[1]), "+f"(d[2]), "+f"(d[3])
                 : "r"(a[0]), "r"(a[1]), "r"(a[2]), "r"(a[3]), "r"(b0), "r"(b1));
}
__device__ __forceinline__ float fast_tanh(float x) {
    float e = __expf(2.0f * x);
    return 1.0f - __fdividef(2.0f, e + 1.0f);
}
__device__ __forceinline__ void pack_pair(float x, float y, uint32_t& hi, uint32_t& lo) {
    asm("cvt.rn.bf16x2.f32 %0, %1, %2;" : "=r"(hi) : "f"(y), "f"(x));
    float xh = __uint_as_float(hi << 16);
    float yh = __uint_as_float(hi & 0xffff0000u);
    float xl = x - xh, yl = y - yh;
    asm("cvt.rn.bf16x2.f32 %0, %1, %2;" : "=r"(lo) : "f"(yl), "f"(xl));
}
__device__ __forceinline__ void split_pair(float a, float b, uint32_t& hi, uint32_t& lo) {
    pack_pair(a, b, hi, lo);
}

#define MBAR_INIT(sa, cnt) \
    asm volatile("mbarrier.init.shared.b64 [%0], %1;" :: "r"(sa), "r"(cnt) : "memory")
#define MBAR_ARRIVE(sa) \
    asm volatile("mbarrier.arrive.shared.b64 _, [%0];" :: "r"(sa) : "memory")
#define MBAR_WAIT(sa, ph) do { \
    asm volatile("{\n\t.reg .pred P;\n\tWL%=:\n\t" \
        "mbarrier.try_wait.parity.acquire.cta.shared::cta.b64 P, [%0], %1, 0x989680;\n\t" \
        "@!P bra WL%=;\n\t}" :: "r"(sa), "r"(ph) : "memory"); \
} while (0)

// d += A x B with A fragments in registers (hi+lo passes), B planes in smem
__device__ __forceinline__ void mm3_reg(float d[8][4],
                                        const uint32_t aH[4][4], const uint32_t aL[4][4],
                                        uint32_t bH, uint32_t bL, uint32_t boff) {
    #pragma unroll
    for (int kc = 0; kc < 4; ++kc) {
        #pragma unroll
        for (int np = 0; np < 4; ++np) {
            uint32_t bf[4];
            uint32_t o = boff + kc * 32 + np * (16 * ACT_LD);
            ldsm4(bH + o, bf);
            mma16816(d[np*2],   aH[kc], bf[0], bf[1]);
            mma16816(d[np*2+1], aH[kc], bf[2], bf[3]);
            mma16816(d[np*2],   aL[kc], bf[0], bf[1]);
            mma16816(d[np*2+1], aL[kc], bf[2], bf[3]);
            ldsm4(bL + o, bf);
            mma16816(d[np*2],   aH[kc], bf[0], bf[1]);
            mma16816(d[np*2+1], aH[kc], bf[2], bf[3]);
        }
    }
}
__device__ __forceinline__ void mm3_dual_reg(float ds[8][4], float dr[8][4],
                                             const uint32_t aH[4][4], const uint32_t aL[4][4],
                                             uint32_t sH, uint32_t sL,
                                             uint32_t rH, uint32_t rL, uint32_t boff) {
    #pragma unroll
    for (int kc = 0; kc < 4; ++kc) {
        #pragma unroll
        for (int np = 0; np < 4; ++np) {
            uint32_t bf[4];
            uint32_t o = boff + kc * 32 + np * (16 * ACT_LD);
            ldsm4(sH + o, bf);
            mma16816(ds[np*2],   aH[kc], bf[0], bf[1]);
            mma16816(ds[np*2+1], aH[kc], bf[2], bf[3]);
            mma16816(ds[np*2],   aL[kc], bf[0], bf[1]);
            mma16816(ds[np*2+1], aL[kc], bf[2], bf[3]);
            ldsm4(sL + o, bf);
            mma16816(ds[np*2],   aH[kc], bf[0], bf[1]);
            mma16816(ds[np*2+1], aH[kc], bf[2], bf[3]);
            ldsm4(rH + o, bf);
            mma16816(dr[np*2],   aH[kc], bf[0], bf[1]);
            mma16816(dr[np*2+1], aH[kc], bf[2], bf[3]);
            mma16816(dr[np*2],   aL[kc], bf[0], bf[1]);
            mma16816(dr[np*2+1], aL[kc], bf[2], bf[3]);
            ldsm4(rL + o, bf);
            mma16816(dr[np*2],   aH[kc], bf[0], bf[1]);
            mma16816(dr[np*2+1], aH[kc], bf[2], bf[3]);
        }
    }
}
// causal: d += A x B, A planes in smem (K = 80 -> 5 k-chunks)
__device__ __forceinline__ void mm3_smem(float d[8][4],
                                         uint32_t aH, uint32_t aL,
                                         uint32_t bH, uint32_t bL,
                                         uint32_t aoff, uint32_t boff) {
    #pragma unroll
    for (int kc = 0; kc < 5; ++kc) {
        uint32_t afH[4], afL[4];
        ldsm4(aH + aoff + kc * 32, afH);
        ldsm4(aL + aoff + kc * 32, afL);
        #pragma unroll
        for (int np = 0; np < 4; ++np) {
            uint32_t bf[4];
            uint32_t o = boff + kc * 32 + np * (16 * WC_LD);
            ldsm4(bH + o, bf);
            mma16816(d[np*2],   afH, bf[0], bf[1]);
            mma16816(d[np*2+1], afH, bf[2], bf[3]);
            mma16816(d[np*2],   afL, bf[0], bf[1]);
            mma16816(d[np*2+1], afL, bf[2], bf[3]);
            ldsm4(bL + o, bf);
            mma16816(d[np*2],   afH, bf[0], bf[1]);
            mma16816(d[np*2+1], afH, bf[2], bf[3]);
        }
    }
}

__device__ __forceinline__ void stage_w(const float* __restrict__ w, char* sm,
                                        int hiOff, int loOff, int tid) {
    const float4* w4 = (const float4*)w;
    #pragma unroll
    for (int i = tid; i < 1024; i += 128) {
        float4 v = w4[i];
        uint32_t h0, l0, h1, l1;
        split_pair(v.x, v.y, h0, l0);
        split_pair(v.z, v.w, h1, l1);
        int off = (i >> 4) * ACT_LD + (i & 15) * 8;
        *(uint2*)(sm + hiOff + off) = make_uint2(h0, h1);
        *(uint2*)(sm + loOff + off) = make_uint2(l0, l1);
    }
}

__global__ __launch_bounds__(NTH, 1)
void wavenet_pipe(const float* __restrict__ x,
                  const float* __restrict__ w_causal, const float* __restrict__ b_causal,
                  const float* __restrict__ w_dil,    const float* __restrict__ b_dil,
                  const float* __restrict__ w_res,    const float* __restrict__ b_res,
                  const float* __restrict__ w_skip,   const float* __restrict__ b_skip,
                  const float* __restrict__ w_post1,  const float* __restrict__ b_post1,
                  const float* __restrict__ w_post2,  const float* __restrict__ b_post2,
                  float* __restrict__ out, int T)
{
    extern __shared__ char sm[];
    const uint32_t sb = smem_u32(sm);
    const int tid  = threadIdx.x;
    const int wid  = tid >> 5;
    const int lane = tid & 31;
    const int b    = blockIdx.y;
    const long t0  = (long)blockIdx.x * 128;
    const bool is_compute = (wid < 8);
    const int m0   = wid * 16;

    const uint32_t FULL0  = sb + OFF_MB + 0;
    const uint32_t EMPTY0 = sb + OFF_MB + 8;
    const uint32_t FULL1  = sb + OFF_MB + 16;
    const uint32_t EMPTY1 = sb + OFF_MB + 24;

    const uint32_t b_off  = (uint32_t)((lane & 7) + ((lane >> 4) & 1) * 8) * ACT_LD
                          + (((lane >> 3) & 1) << 4);
    const uint32_t a_offc = (uint32_t)(m0 + (lane & 15)) * WC_LD + ((lane >> 4) << 4);
    const uint32_t b_offc = (uint32_t)((lane & 7) + ((lane >> 4) & 1) * 8) * WC_LD
                          + (((lane >> 3) & 1) << 4);
    const int r0 = (lane >> 2);
    const int cq = (lane & 3) * 2;

    if (tid == 0) {
        MBAR_INIT(FULL0, 128); MBAR_INIT(FULL1, 128);
        MBAR_INIT(EMPTY0, 256); MBAR_INIT(EMPTY1, 256);
    }

    // ---- stage x planes (WBUF1 alias) + w_causal planes (scratch) + bc ----
    const float* xg = x + (size_t)b * 80 * (size_t)T + t0;
    for (int i = tid; i < 80 * 128; i += NTH) {
        int ch = i >> 7, t = i & 127;
        float v = xg[(size_t)ch * T + t];
        __nv_bfloat16 hb = __float2bfloat16_rn(v);
        __nv_bfloat16 lb = __float2bfloat16_rn(v - __bfloat162float(hb));
        int off = t * WC_LD + ch * 2;
        *(__nv_bfloat16*)(sm + X_HI + off) = hb;
        *(__nv_bfloat16*)(sm + X_LO + off) = lb;
    }
    for (int i = tid; i < 64 * 80; i += NTH) {
        int o = i / 80, k = i - o * 80;
        float v = w_causal[i];
        __nv_bfloat16 hb = __float2bfloat16_rn(v);
        __nv_bfloat16 lb = __float2bfloat16_rn(v - __bfloat162float(hb));
        int off = o * WC_LD + k * 2;
        *(__nv_bfloat16*)(sm + WCA_HI + off) = hb;
        *(__nv_bfloat16*)(sm + WCA_LO + off) = lb;
    }
    if (tid < 64) ((float*)(sm + OFF_BC))[tid] = b_causal[tid];
    __syncthreads();   // the ONLY full barrier

    if (!is_compute) {
        // ================= producer role =================
        int p = tid - 256;
        #pragma unroll 1
        for (int pl = 0; pl <= L_LAYERS; ++pl) {
            int pb = pl & 1;
            if (pl >= 1) {
                int par = pb ? ((pl >> 1) & 1) : (((pl >> 1) + 1) & 1);
                MBAR_WAIT(pb ? EMPTY1 : EMPTY0, par);
            }
            char* wn = sm + (pb ? WBUF1 : WBUF0);
            if (pl < L_LAYERS) {
                stage_w(w_dil  + pl * 4096, wn, 0,     9216,  p);
                stage_w(w_skip + pl * 4096, wn, 18432, 27648, p);
                stage_w(w_res  + pl * 4096, wn, 36864, 46080, p);
                if (p < 64)  ((float*)(sm + OFF_BDR + pb * 512))[p]            = b_dil[pl * 64 + p];
                else         ((float*)(sm + OFF_BDR + pb * 512 + 256))[p - 64] = b_res[pl * 64 + p - 64];
            } else {
                stage_w(w_post1, wn, 0, 9216, p);
                if (p < 64) {
                    float s = 0.0f;
                    #pragma unroll
                    for (int ll = 0; ll < L_LAYERS; ++ll) s += b_skip[ll * 64 + p];
                    ((float*)(sm + OFF_BTOT))[p] = s;
                    ((float*)(sm + OFF_BP1))[p]  = b_post1[p];
                    ((float*)(sm + OFF_WP2))[p]  = w_post2[p];
                }
                if (p == 64) ((float*)(sm + OFF_B2))[0] = b_post2[0];
            }
            MBAR_ARRIVE(pb ? FULL1 : FULL0);
        }
        return;
    }

    // ================= compute role =================
    float h[8][4], skip[8][4];
    uint32_t ahH[4][4], ahL[4][4];
    #pragma unroll
    for (int n = 0; n < 8; ++n)
        #pragma unroll
        for (int j = 0; j < 4; ++j) { h[n][j] = 0.0f; skip[n][j] = 0.0f; }

    // causal: h = Wc @ x + bc; build h fragments
    mm3_smem(h, sb + X_HI, sb + X_LO, sb + WCA_HI, sb + WCA_LO, a_offc, b_offc);
    #pragma unroll
    for (int n = 0; n < 8; ++n) {
        float2 bc = *(const float2*)(sm + OFF_BC + (n * 8 + cq) * 4);
        h[n][0] += bc.x; h[n][1] += bc.y; h[n][2] += bc.x; h[n][3] += bc.y;
        int kc = n >> 1, o = (n & 1) * 2;
        pack_pair(h[n][0], h[n][1], ahH[kc][o],   ahL[kc][o]);
        pack_pair(h[n][2], h[n][3], ahH[kc][o+1], ahL[kc][o+1]);
    }
    MBAR_ARRIVE(EMPTY1);   // release X planes (WBUF1 alias) for producer pl=1

    #pragma unroll 1
    for (int l = 0; l < L_LAYERS; ++l) {
        const int lb_ = l & 1;
        const uint32_t wb = sb + (uint32_t)(lb_ ? WBUF1 : WBUF0);
        MBAR_WAIT(lb_ ? FULL1 : FULL0, (l >> 1) & 1);

        // ---- f = tanh(Wd @ h + bd) -> A fragments ----
        float d[8][4];
        #pragma unroll
        for (int n = 0; n < 8; ++n)
            #pragma unroll
            for (int j = 0; j < 4; ++j) d[n][j] = 0.0f;
        mm3_reg(d, ahH, ahL, wb + 0, wb + 9216, b_off);

        uint32_t afH[4][4], afL[4][4];
        {
            const char* bdp = sm + OFF_BDR + lb_ * 512;
            #pragma unroll
            for (int n = 0; n < 8; ++n) {
                float2 bd = *(const float2*)(bdp + (n * 8 + cq) * 4);
                float v0 = fast_tanh(d[n][0] + bd.x), v1 = fast_tanh(d[n][1] + bd.y);
                float v2 = fast_tanh(d[n][2] + bd.x), v3 = fast_tanh(d[n][3] + bd.y);
                int kc = n >> 1, o = (n & 1) * 2;
                pack_pair(v0, v1, afH[kc][o],   afL[kc][o]);
                pack_pair(v2, v3, afH[kc][o+1], afL[kc][o+1]);
            }
        }

        // ---- skip += Ws @ f ; h += Wr @ f + br ----
        #pragma unroll
        for (int n = 0; n < 8; ++n)
            #pragma unroll
            for (int j = 0; j < 4; ++j) d[n][j] = 0.0f;
        mm3_dual_reg(skip, d, afH, afL,
                     wb + 18432, wb + 27648, wb + 36864, wb + 46080, b_off);
        {
            const char* brp = sm + OFF_BDR + lb_ * 512 + 256;
            #pragma unroll
            for (int n = 0; n < 8; ++n) {
                float2 br2 = *(const float2*)(brp + (n * 8 + cq) * 4);
                h[n][0] += d[n][0] + br2.x; h[n][1] += d[n][1] + br2.y;
                h[n][2] += d[n][2] + br2.x; h[n][3] += d[n][3] + br2.y;
                int kc = n >> 1, o = (n & 1) * 2;
                pack_pair(h[n][0], h[n][1], ahH[kc][o],   ahL[kc][o]);
                pack_pair(h[n][2], h[n][3], ahH[kc][o+1], ahL[kc][o+1]);
            }
        }
        MBAR_ARRIVE(lb_ ? EMPTY1 : EMPTY0);
    }

    // ================= post =================
    // s = tanh(skip + btot); W1 staged in buf0 dil slot by producer pl=20
    MBAR_WAIT(FULL0, (L_LAYERS >> 1) & 1);
    uint32_t afH[4][4], afL[4][4];
    #pragma unroll
    for (int n = 0; n < 8; ++n) {
        float2 bt = *(const float2*)(sm + OFF_BTOT + (n * 8 + cq) * 4);
        float v0 = fast_tanh(skip[n][0] + bt.x), v1 = fast_tanh(skip[n][1] + bt.y);
        float v2 = fast_tanh(skip[n][2] + bt.x), v3 = fast_tanh(skip[n][3] + bt.y);
        int kc = n >> 1, o = (n & 1) * 2;
        pack_pair(v0, v1, afH[kc][o],   afL[kc][o]);
        pack_pair(v2, v3, afH[kc][o+1], afL[kc][o+1]);
    }
    float d[8][4];
    #pragma unroll
    for (int n = 0; n < 8; ++n)
        #pragma unroll
        for (int j = 0; j < 4; ++j) d[n][j] = 0.0f;
    mm3_reg(d, afH, afL, sb + WBUF0 + 0, sb + WBUF0 + 9216, b_off);
    {
        float p0 = 0.0f, p1 = 0.0f;
        #pragma unroll
        for (int n = 0; n < 8; ++n) {
            int c0 = n * 8 + cq;
            float2 bp = *(const float2*)(sm + OFF_BP1 + c0 * 4);
            float2 w2 = *(const float2*)(sm + OFF_WP2 + c0 * 4);
            p0 = fmaf(w2.x, fast_tanh(d[n][0] + bp.x), p0);
            p0 = fmaf(w2.y, fast_tanh(d[n][1] + bp.y), p0);
            p1 = fmaf(w2.x, fast_tanh(d[n][2] + bp.x), p1);
            p1 = fmaf(w2.y, fast_tanh(d[n][3] + bp.y), p1);
        }
        p0 += __shfl_xor_sync(0xFFFFFFFFu, p0, 1);
        p0 += __shfl_xor_sync(0xFFFFFFFFu, p0, 2);
        p1 += __shfl_xor_sync(0xFFFFFFFFu, p1, 1);
        p1 += __shfl_xor_sync(0xFFFFFFFFu, p1, 2);
        if ((lane & 3) == 0) {
            float b2 = ((const float*)(sm + OFF_B2))[0];
            size_t base = (size_t)b * T + t0 + m0;
            out[base + r0]     = b2 + p0;
            out[base + r0 + 8] = b2 + p1;
        }
    }
}

extern "C" void kernel_launch(void* const* d_in, const int* in_sizes, int n_in,
                              void* d_out, int out_size)
{
    const float* x        = (const float*)d_in[0];
    const float* w_causal = (const float*)d_in[1];
    const float* b_causal = (const float*)d_in[2];
    const float* w_dil    = (const float*)d_in[3];
    const float* b_dil    = (const float*)d_in[4];
    const float* w_res    = (const float*)d_in[5];
    const float* b_res    = (const float*)d_in[6];
    const float* w_skip   = (const float*)d_in[7];
    const float* b_skip   = (const float*)d_in[8];
    const float* w_post1  = (const float*)d_in[9];
    const float* b_post1  = (const float*)d_in[10];
    const float* w_post2  = (const float*)d_in[11];
    const float* b_post2  = (const float*)d_in[12];
    float* out = (float*)d_out;

    const int B = 4;
    const int T = out_size / B;   // 65536

    cudaFuncSetAttribute(wavenet_pipe,
                         cudaFuncAttributeMaxDynamicSharedMemorySize, SMEM_BYTES);

    dim3 grid(T / 128, B);
    wavenet_pipe<<<grid, NTH, SMEM_BYTES>>>(
        x, w_causal, b_causal, w_dil, b_dil, w_res, b_res,
        w_skip, b_skip, w_post1, b_post1, w_post2, b_post2, out, T);
}

// round 8
// speedup vs baseline: 1.0079x; 1.0079x over previous
#include <cuda_runtime.h>
#include <cuda_bf16.h>
#include <cstdint>

#define L_LAYERS 20
#define ACT_LD   144       // weight plane row stride (64*2B + 16 pad)
#define WC_LD    176       // causal plane row stride (80*2B + 16 pad)
#define NTH      384       // 8 compute warps + 4 producer warps

// ---- smem layout (bytes) ----
#define WBUF0    0
#define WBUF1    55296
#define WCA_HI   110592
#define WCA_LO   121856
#define OFF_BDR  133120    // [2 buf][bd 64 | br 64] f32
#define OFF_BC   134144
#define OFF_BTOT 134400
#define OFF_BP1  134656
#define OFF_WP2  134912
#define OFF_B2   135168
#define SMEM_BYTES 135296
// causal x planes alias WBUF1
#define X_HI     55296
#define X_LO     77824

__device__ __forceinline__ uint32_t smem_u32(const void* p) {
    uint32_t a;
    asm("{ .reg .u64 t; cvta.to.shared.u64 t, %1; cvt.u32.u64 %0, t; }" : "=r"(a) : "l"(p));
    return a;
}
__device__ __forceinline__ void ldsm4(uint32_t addr, uint32_t r[4]) {
    asm volatile("ldmatrix.sync.aligned.m8n8.x4.shared.b16 {%0,%1,%2,%3}, [%4];"
                 : "=r"(r[0]), "=r"(r[1]), "=r"(r[2]), "=r"(r[3]) : "r"(addr));
}
__device__ __forceinline__ void mma16816(float d[4], const uint32_t a[4],
                                         uint32_t b0, uint32_t b1) {
    asm volatile("mma.sync.aligned.m16n8k16.row.col.f32.bf16.bf16.f32 "
                 "{%0,%1,%2,%3},{%4,%5,%6,%7},{%8,%9},{%0,%1,%2,%3};"
                 : "+f"(d[0]), "+f"(d[1]), "+f"(d[2]), "+f"(d[3])
                 : "r"(a[0]), "r"(a[1]), "r"(a[2]), "r"(a[3]), "r"(b0), "r"(b1));
}
// single-MUFU tanh (layer loop); abs err ~2^-10.7
__device__ __forceinline__ float tanha(float x) {
    float y; asm("tanh.approx.f32 %0, %1;" : "=f"(y) : "f"(x)); return y;
}
// precise-ish tanh for post network (error here is not amplified by 20 layers)
__device__ __forceinline__ float fast_tanh(float x) {
    float e = __expf(2.0f * x);
    return 1.0f - __fdividef(2.0f, e + 1.0f);
}
__device__ __forceinline__ void pack_pair(float x, float y, uint32_t& hi, uint32_t& lo) {
    asm("cvt.rn.bf16x2.f32 %0, %1, %2;" : "=r"(hi) : "f"(y), "f"(x));
    float xh = __uint_as_float(hi << 16);
    float yh = __uint_as_float(hi & 0xffff0000u);
    float xl = x - xh, yl = y - yh;
    asm("cvt.rn.bf16x2.f32 %0, %1, %2;" : "=r"(lo) : "f"(yl), "f"(xl));
}
__device__ __forceinline__ void split_pair(float a, float b, uint32_t& hi, uint32_t& lo) {
    pack_pair(a, b, hi, lo);
}

// d += A x B with A fragments in registers (hi+lo passes), B planes in smem
__device__ __forceinline__ void mm3_reg(float d[8][4],
                                        const uint32_t aH[4][4], const uint32_t aL[4][4],
                                        uint32_t bH, uint32_t bL, uint32_t boff) {
    #pragma unroll
    for (int kc = 0; kc < 4; ++kc) {
        #pragma unroll
        for (int np = 0; np < 4; ++np) {
            uint32_t bf[4];
            uint32_t o = boff + kc * 32 + np * (16 * ACT_LD);
            ldsm4(bH + o, bf);
            mma16816(d[np*2],   aH[kc], bf[0], bf[1]);
            mma16816(d[np*2+1], aH[kc], bf[2], bf[3]);
            mma16816(d[np*2],   aL[kc], bf[0], bf[1]);
            mma16816(d[np*2+1], aL[kc], bf[2], bf[3]);
            ldsm4(bL + o, bf);
            mma16816(d[np*2],   aH[kc], bf[0], bf[1]);
            mma16816(d[np*2+1], aH[kc], bf[2], bf[3]);
        }
    }
}
__device__ __forceinline__ void mm3_dual_reg(float ds[8][4], float dr[8][4],
                                             const uint32_t aH[4][4], const uint32_t aL[4][4],
                                             uint32_t sH, uint32_t sL,
                                             uint32_t rH, uint32_t rL, uint32_t boff) {
    #pragma unroll
    for (int kc = 0; kc < 4; ++kc) {
        #pragma unroll
        for (int np = 0; np < 4; ++np) {
            uint32_t bf[4];
            uint32_t o = boff + kc * 32 + np * (16 * ACT_LD);
            ldsm4(sH + o, bf);
            mma16816(ds[np*2],   aH[kc], bf[0], bf[1]);
            mma16816(ds[np*2+1], aH[kc], bf[2], bf[3]);
            mma16816(ds[np*2],   aL[kc], bf[0], bf[1]);
            mma16816(ds[np*2+1], aL[kc], bf[2], bf[3]);
            ldsm4(sL + o, bf);
            mma16816(ds[np*2],   aH[kc], bf[0], bf[1]);
            mma16816(ds[np*2+1], aH[kc], bf[2], bf[3]);
            ldsm4(rH + o, bf);
            mma16816(dr[np*2],   aH[kc], bf[0], bf[1]);
            mma16816(dr[np*2+1], aH[kc], bf[2], bf[3]);
            mma16816(dr[np*2],   aL[kc], bf[0], bf[1]);
            mma16816(dr[np*2+1], aL[kc], bf[2], bf[3]);
            ldsm4(rL + o, bf);
            mma16816(dr[np*2],   aH[kc], bf[0], bf[1]);
            mma16816(dr[np*2+1], aH[kc], bf[2], bf[3]);
        }
    }
}
// causal: d += A x B, A planes in smem (K = 80 -> 5 k-chunks)
__device__ __forceinline__ void mm3_smem(float d[8][4],
                                         uint32_t aH, uint32_t aL,
                                         uint32_t bH, uint32_t bL,
                                         uint32_t aoff, uint32_t boff) {
    #pragma unroll
    for (int kc = 0; kc < 5; ++kc) {
        uint32_t afH[4], afL[4];
        ldsm4(aH + aoff + kc * 32, afH);
        ldsm4(aL + aoff + kc * 32, afL);
        #pragma unroll
        for (int np = 0; np < 4; ++np) {
            uint32_t bf[4];
            uint32_t o = boff + kc * 32 + np * (16 * WC_LD);
            ldsm4(bH + o, bf);
            mma16816(d[np*2],   afH, bf[0], bf[1]);
            mma16816(d[np*2+1], afH, bf[2], bf[3]);
            mma16816(d[np*2],   afL, bf[0], bf[1]);
            mma16816(d[np*2+1], afL, bf[2], bf[3]);
            ldsm4(bL + o, bf);
            mma16816(d[np*2],   afH, bf[0], bf[1]);
            mma16816(d[np*2+1], afH, bf[2], bf[3]);
        }
    }
}

__device__ __forceinline__ void stage_w(const float* __restrict__ w, char* sm,
                                        int hiOff, int loOff, int tid) {
    const float4* w4 = (const float4*)w;
    #pragma unroll
    for (int i = tid; i < 1024; i += 128) {
        float4 v = w4[i];
        uint32_t h0, l0, h1, l1;
        split_pair(v.x, v.y, h0, l0);
        split_pair(v.z, v.w, h1, l1);
        int off = (i >> 4) * ACT_LD + (i & 15) * 8;
        *(uint2*)(sm + hiOff + off) = make_uint2(h0, h1);
        *(uint2*)(sm + loOff + off) = make_uint2(l0, l1);
    }
}

__global__ __launch_bounds__(NTH, 1)
void wavenet_r8(const float* __restrict__ x,
                const float* __restrict__ w_causal, const float* __restrict__ b_causal,
                const float* __restrict__ w_dil,    const float* __restrict__ b_dil,
                const float* __restrict__ w_res,    const float* __restrict__ b_res,
                const float* __restrict__ w_skip,   const float* __restrict__ b_skip,
                const float* __restrict__ w_post1,  const float* __restrict__ b_post1,
                const float* __restrict__ w_post2,  const float* __restrict__ b_post2,
                float* __restrict__ out, int T)
{
    extern __shared__ char sm[];
    const uint32_t sb = smem_u32(sm);
    const int tid  = threadIdx.x;
    const int wid  = tid >> 5;
    const int lane = tid & 31;
    const int b    = blockIdx.y;
    const long t0  = (long)blockIdx.x * 128;
    const bool is_compute = (wid < 8);
    const int m0   = wid * 16;

    const uint32_t b_off  = (uint32_t)((lane & 7) + ((lane >> 4) & 1) * 8) * ACT_LD
                          + (((lane >> 3) & 1) << 4);
    const uint32_t a_offc = (uint32_t)(m0 + (lane & 15)) * WC_LD + ((lane >> 4) << 4);
    const uint32_t b_offc = (uint32_t)((lane & 7) + ((lane >> 4) & 1) * 8) * WC_LD
                          + (((lane >> 3) & 1) << 4);
    const int r0 = (lane >> 2);
    const int cq = (lane & 3) * 2;

    // ---- stage x planes (WBUF1 alias) + w_causal planes + bc ----
    const float* xg = x + (size_t)b * 80 * (size_t)T + t0;
    for (int i = tid; i < 80 * 128; i += NTH) {
        int ch = i >> 7, t = i & 127;
        float v = xg[(size_t)ch * T + t];
        __nv_bfloat16 hb = __float2bfloat16_rn(v);
        __nv_bfloat16 lb = __float2bfloat16_rn(v - __bfloat162float(hb));
        int off = t * WC_LD + ch * 2;
        *(__nv_bfloat16*)(sm + X_HI + off) = hb;
        *(__nv_bfloat16*)(sm + X_LO + off) = lb;
    }
    for (int i = tid; i < 64 * 80; i += NTH) {
        int o = i / 80, k = i - o * 80;
        float v = w_causal[i];
        __nv_bfloat16 hb = __float2bfloat16_rn(v);
        __nv_bfloat16 lb = __float2bfloat16_rn(v - __bfloat162float(hb));
        int off = o * WC_LD + k * 2;
        *(__nv_bfloat16*)(sm + WCA_HI + off) = hb;
        *(__nv_bfloat16*)(sm + WCA_LO + off) = lb;
    }
    if (tid < 64) ((float*)(sm + OFF_BC))[tid] = b_causal[tid];
    __syncthreads();

    float h[8][4], skip[8][4];
    uint32_t ahH[4][4], ahL[4][4];
    #pragma unroll
    for (int n = 0; n < 8; ++n)
        #pragma unroll
        for (int j = 0; j < 4; ++j) { h[n][j] = 0.0f; skip[n][j] = 0.0f; }

    if (is_compute) {
        mm3_smem(h, sb + X_HI, sb + X_LO, sb + WCA_HI, sb + WCA_LO, a_offc, b_offc);
        #pragma unroll
        for (int n = 0; n < 8; ++n) {
            float2 bc = *(const float2*)(sm + OFF_BC + (n * 8 + cq) * 4);
            h[n][0] += bc.x; h[n][1] += bc.y; h[n][2] += bc.x; h[n][3] += bc.y;
            int kc = n >> 1, o = (n & 1) * 2;
            pack_pair(h[n][0], h[n][1], ahH[kc][o],   ahL[kc][o]);
            pack_pair(h[n][2], h[n][3], ahH[kc][o+1], ahL[kc][o+1]);
        }
    } else {
        int p = tid - 256;
        stage_w(w_dil,  sm, WBUF0 + 0,     WBUF0 + 9216,  p);
        stage_w(w_skip, sm, WBUF0 + 18432, WBUF0 + 27648, p);
        stage_w(w_res,  sm, WBUF0 + 36864, WBUF0 + 46080, p);
        if (p < 64)      ((float*)(sm + OFF_BDR))[p]             = b_dil[p];
        else             ((float*)(sm + OFF_BDR + 256))[p - 64]  = b_res[p - 64];
    }
    __syncthreads();

    // ================= layer loop =================
    #pragma unroll 1
    for (int l = 0; l < L_LAYERS; ++l) {
        const uint32_t wb = sb + (uint32_t)((l & 1) ? WBUF1 : WBUF0);
        if (is_compute) {
            // ---- f = tanh(Wd @ h + bd) (accumulator pre-seeded with bd) ----
            float d[8][4];
            const char* bdp = sm + OFF_BDR + (l & 1) * 512;
            #pragma unroll
            for (int n = 0; n < 8; ++n) {
                float2 bd = *(const float2*)(bdp + (n * 8 + cq) * 4);
                d[n][0] = bd.x; d[n][1] = bd.y; d[n][2] = bd.x; d[n][3] = bd.y;
            }
            mm3_reg(d, ahH, ahL, wb + 0, wb + 9216, b_off);

            uint32_t afH[4][4], afL[4][4];
            #pragma unroll
            for (int n = 0; n < 8; ++n) {
                float v0 = tanha(d[n][0]), v1 = tanha(d[n][1]);
                float v2 = tanha(d[n][2]), v3 = tanha(d[n][3]);
                int kc = n >> 1, o = (n & 1) * 2;
                pack_pair(v0, v1, afH[kc][o],   afL[kc][o]);
                pack_pair(v2, v3, afH[kc][o+1], afL[kc][o+1]);
            }

            // ---- skip += Ws @ f ; h += (Wr @ f + br) (accumulator pre-seeded with br) ----
            const char* brp = sm + OFF_BDR + (l & 1) * 512 + 256;
            #pragma unroll
            for (int n = 0; n < 8; ++n) {
                float2 br2 = *(const float2*)(brp + (n * 8 + cq) * 4);
                d[n][0] = br2.x; d[n][1] = br2.y; d[n][2] = br2.x; d[n][3] = br2.y;
            }
            mm3_dual_reg(skip, d, afH, afL,
                         wb + 18432, wb + 27648, wb + 36864, wb + 46080, b_off);
            #pragma unroll
            for (int n = 0; n < 8; ++n) {
                h[n][0] += d[n][0]; h[n][1] += d[n][1];
                h[n][2] += d[n][2]; h[n][3] += d[n][3];
                int kc = n >> 1, o = (n & 1) * 2;
                pack_pair(h[n][0], h[n][1], ahH[kc][o],   ahL[kc][o]);
                pack_pair(h[n][2], h[n][3], ahH[kc][o+1], ahL[kc][o+1]);
            }
        } else {
            int p = tid - 256;
            int nb = (l + 1) & 1;
            char* wn = sm + (nb ? WBUF1 : WBUF0);
            if (l < L_LAYERS - 1) {
                stage_w(w_dil  + (l + 1) * 4096, wn, 0,     9216,  p);
                stage_w(w_skip + (l + 1) * 4096, wn, 18432, 27648, p);
                stage_w(w_res  + (l + 1) * 4096, wn, 36864, 46080, p);
                if (p < 64)  ((float*)(sm + OFF_BDR + nb * 512))[p]            = b_dil[(l + 1) * 64 + p];
                else         ((float*)(sm + OFF_BDR + nb * 512 + 256))[p - 64] = b_res[(l + 1) * 64 + p - 64];
            } else {
                stage_w(w_post1, wn, 0, 9216, p);
                if (p < 64) {
                    float s = 0.0f;
                    #pragma unroll
                    for (int ll = 0; ll < L_LAYERS; ++ll) s += b_skip[ll * 64 + p];
                    ((float*)(sm + OFF_BTOT))[p] = s;
                    ((float*)(sm + OFF_BP1))[p]  = b_post1[p];
                    ((float*)(sm + OFF_WP2))[p]  = w_post2[p];
                }
                if (p == 64) ((float*)(sm + OFF_B2))[0] = b_post2[0];
            }
        }
        __syncthreads();
    }

    // ================= post =================
    if (is_compute) {
        uint32_t afH[4][4], afL[4][4];
        #pragma unroll
        for (int n = 0; n < 8; ++n) {
            float2 bt = *(const float2*)(sm + OFF_BTOT + (n * 8 + cq) * 4);
            float v0 = fast_tanh(skip[n][0] + bt.x), v1 = fast_tanh(skip[n][1] + bt.y);
            float v2 = fast_tanh(skip[n][2] + bt.x), v3 = fast_tanh(skip[n][3] + bt.y);
            int kc = n >> 1, o = (n & 1) * 2;
            pack_pair(v0, v1, afH[kc][o],   afL[kc][o]);
            pack_pair(v2, v3, afH[kc][o+1], afL[kc][o+1]);
        }

        const uint32_t wb = sb + (uint32_t)((L_LAYERS & 1) ? WBUF1 : WBUF0);
        float d[8][4];
        #pragma unroll
        for (int n = 0; n < 8; ++n) {
            float2 bp = *(const float2*)(sm + OFF_BP1 + (n * 8 + cq) * 4);
            d[n][0] = bp.x; d[n][1] = bp.y; d[n][2] = bp.x; d[n][3] = bp.y;
        }
        mm3_reg(d, afH, afL, wb + 0, wb + 9216, b_off);
        {
            float p0 = 0.0f, p1 = 0.0f;
            #pragma unroll
            for (int n = 0; n < 8; ++n) {
                int c0 = n * 8 + cq;
                float2 w2 = *(const float2*)(sm + OFF_WP2 + c0 * 4);
                p0 = fmaf(w2.x, fast_tanh(d[n][0]), p0);
                p0 = fmaf(w2.y, fast_tanh(d[n][1]), p0);
                p1 = fmaf(w2.x, fast_tanh(d[n][2]), p1);
                p1 = fmaf(w2.y, fast_tanh(d[n][3]), p1);
            }
            p0 += __shfl_xor_sync(0xFFFFFFFFu, p0, 1);
            p0 += __shfl_xor_sync(0xFFFFFFFFu, p0, 2);
            p1 += __shfl_xor_sync(0xFFFFFFFFu, p1, 1);
            p1 += __shfl_xor_sync(0xFFFFFFFFu, p1, 2);
            if ((lane & 3) == 0) {
                float b2 = ((const float*)(sm + OFF_B2))[0];
                size_t base = (size_t)b * T + t0 + m0;
                out[base + r0]     = b2 + p0;
                out[base + r0 + 8] = b2 + p1;
            }
        }
    }
}

extern "C" void kernel_launch(void* const* d_in, const int* in_sizes, int n_in,
                              void* d_out, int out_size)
{
    const float* x        = (const float*)d_in[0];
    const float* w_causal = (const float*)d_in[1];
    const float* b_causal = (const float*)d_in[2];
    const float* w_dil    = (const float*)d_in[3];
    const float* b_dil    = (const float*)d_in[4];
    const float* w_res    = (const float*)d_in[5];
    const float* b_res    = (const float*)d_in[6];
    const float* w_skip   = (const float*)d_in[7];
    const float* b_skip   = (const float*)d_in[8];
    const float* w_post1  = (const float*)d_in[9];
    const float* b_post1  = (const float*)d_in[10];
    const float* w_post2  = (const float*)d_in[11];
    const float* b_post2  = (const float*)d_in[12];
    float* out = (float*)d_out;

    const int B = 4;
    const int T = out_size / B;   // 65536

    cudaFuncSetAttribute(wavenet_r8,
                         cudaFuncAttributeMaxDynamicSharedMemorySize, SMEM_BYTES);

    dim3 grid(T / 128, B);
    wavenet_r8<<<grid, NTH, SMEM_BYTES>>>(
        x, w_causal, b_causal, w_dil, b_dil, w_res, b_res,
        w_skip, b_skip, w_post1, b_post1, w_post2, b_post2, out, T);
}